// round 5
// baseline (speedup 1.0000x reference)
#include <cuda_runtime.h>
#include <cstdint>

#define MPTS 131072
#define BM 128
#define BN 256
#define BK 32
#define STAGES 3
#define AP 36                      // A smem pitch (floats): bank = 4q+j bijective, 16B-aligned
#define BP 264                     // B smem pitch (floats): bank = 8j+q bijective, 16B-aligned
#define A_STAGE_F (BM * AP)        // 4608 floats
#define B_STAGE_F (BK * BP)        // 8448 floats
#define SMEM_BYTES (STAGES * (A_STAGE_F + B_STAGE_F) * 4)   // 156672

// ---- scratch (device globals; no allocation allowed) ----
__device__ float g_xr[(size_t)MPTS * 288];    // rounded [x|pos|0] padded to K=288
__device__ float g_h1[(size_t)MPTS * 256];
__device__ float g_h2[(size_t)MPTS * 512];
__device__ float g_w1r[288 * 256];
__device__ float g_w2r[256 * 512];
__device__ float g_w3r[512 * 1024];

// ---------------- helpers ----------------
__device__ __forceinline__ uint32_t s2u(const void* p) {
    uint32_t a;
    asm("{ .reg .u64 t; cvta.to.shared.u64 t, %1; cvt.u32.u64 %0, t; }" : "=r"(a) : "l"(p));
    return a;
}
__device__ __forceinline__ float tf32r(float x) {
    uint32_t u;
    asm("cvt.rna.tf32.f32 %0, %1;" : "=r"(u) : "f"(x));
    return __uint_as_float(u);
}
__device__ __forceinline__ void cp16(uint32_t dst, const void* src) {
    asm volatile("cp.async.cg.shared.global [%0], [%1], 16;" :: "r"(dst), "l"(src));
}
__device__ __forceinline__ void mma8(float* c, const uint32_t* a, const uint32_t* b) {
    asm volatile("mma.sync.aligned.m16n8k8.row.col.f32.tf32.tf32.f32 "
        "{%0,%1,%2,%3}, {%4,%5,%6,%7}, {%8,%9}, {%0,%1,%2,%3};"
        : "+f"(c[0]), "+f"(c[1]), "+f"(c[2]), "+f"(c[3])
        : "r"(a[0]), "r"(a[1]), "r"(a[2]), "r"(a[3]), "r"(b[0]), "r"(b[1]));
}

// ---------------- prep kernels ----------------
__global__ void prep_x_kernel(const float* __restrict__ x, const float* __restrict__ pos,
                              float* __restrict__ xr, float* __restrict__ out, int out_n) {
    int i = blockIdx.x * blockDim.x + threadIdx.x;
    if (i < out_n) out[i] = 0.0f;
    if (i >= MPTS * 288) return;
    int r = i / 288, c = i % 288;
    float v = 0.0f;
    if (c < 256)      v = tf32r(x[(size_t)r * 256 + c]);
    else if (c < 259) v = tf32r(pos[(size_t)r * 3 + (c - 256)]);
    xr[i] = v;
}
__global__ void wround_kernel(const float* __restrict__ W, float* __restrict__ out,
                              int K, int N, int KP) {
    int i = blockIdx.x * blockDim.x + threadIdx.x;
    if (i >= KP * N) return;
    int k = i / N;
    out[i] = (k < K) ? tf32r(W[i]) : 0.0f;
}

// ---------------- fused GEMM: C = relu(A @ B + bias) ----------------
// CTA tile 128x256, warp tile 64x64 (warps 2x4). A row-major, B [K,N] row-major.
template<int SEGMAX>
__global__ __launch_bounds__(256, 1)
void tc_gemm(const float* __restrict__ A, const float* __restrict__ B,
             const float* __restrict__ bias, float* __restrict__ C,
             int N, int lda, int nCh)
{
    extern __shared__ float sm[];
    float* As = sm;
    float* Bs = sm + STAGES * A_STAGE_F;
    const uint32_t sbA = s2u(As), sbB = s2u(Bs);
    const int tid = threadIdx.x;
    const int lane = tid & 31, wid = tid >> 5;
    const int wm = (wid >> 2) * 64;       // 2 warp-rows
    const int wn = (wid & 3) * 64;        // 4 warp-cols
    const int row0 = blockIdx.y * BM, col0 = blockIdx.x * BN;

    float acc[4][8][4];
    #pragma unroll
    for (int i = 0; i < 4; i++)
        #pragma unroll
        for (int j = 0; j < 8; j++)
            #pragma unroll
            for (int k = 0; k < 4; k++) acc[i][j][k] = 0.0f;

    auto load_stage = [&](int kc, int s) {
        const int kb = kc * BK;
        #pragma unroll
        for (int i = 0; i < 4; i++) {                   // A: 128x32 = 1024 f4
            int idx = i * 256 + tid;
            int r = idx >> 3, c4 = idx & 7;
            cp16(sbA + (s * A_STAGE_F + r * AP + c4 * 4) * 4,
                 &A[(size_t)(row0 + r) * lda + kb + c4 * 4]);
        }
        #pragma unroll
        for (int i = 0; i < 8; i++) {                   // B: 32x256 = 2048 f4
            int idx = i * 256 + tid;
            int kr = idx >> 6, n4 = idx & 63;
            cp16(sbB + (s * B_STAGE_F + kr * BP + n4 * 4) * 4,
                 &B[(size_t)(kb + kr) * N + col0 + n4 * 4]);
        }
        asm volatile("cp.async.commit_group;" ::: "memory");
    };

    load_stage(0, 0);
    load_stage(1, 1);

    for (int kc = 0; kc < nCh; kc++) {
        if (kc + 1 < nCh) asm volatile("cp.async.wait_group 1;" ::: "memory");
        else              asm volatile("cp.async.wait_group 0;" ::: "memory");
        __syncthreads();
        if (kc + 2 < nCh) load_stage(kc + 2, (kc + 2) % STAGES);

        const float* a_s = As + (kc % STAGES) * A_STAGE_F;
        const float* b_s = Bs + (kc % STAGES) * B_STAGE_F;
        #pragma unroll
        for (int kq = 0; kq < 4; kq++) {
            const int k0 = kq * 8;
            uint32_t af[4][4], bf[8][2];
            #pragma unroll
            for (int im = 0; im < 4; im++) {
                const float* p = a_s + (size_t)(wm + im * 16 + (lane >> 2)) * AP + k0 + (lane & 3);
                af[im][0] = __float_as_uint(p[0]);
                af[im][1] = __float_as_uint(p[8 * AP]);
                af[im][2] = __float_as_uint(p[4]);
                af[im][3] = __float_as_uint(p[8 * AP + 4]);
            }
            #pragma unroll
            for (int in = 0; in < 8; in++) {
                const float* p = b_s + (size_t)(k0 + (lane & 3)) * BP + wn + in * 8 + (lane >> 2);
                bf[in][0] = __float_as_uint(p[0]);
                bf[in][1] = __float_as_uint(p[4 * BP]);
            }
            #pragma unroll
            for (int im = 0; im < 4; im++)
                #pragma unroll
                for (int in = 0; in < 8; in++)
                    mma8(acc[im][in], af[im], bf[in]);
        }
    }

    // ---- epilogue ----
    if (!SEGMAX) {
        #pragma unroll
        for (int in = 0; in < 8; in++) {
            const int c = col0 + wn + in * 8 + (lane & 3) * 2;
            const float b0 = bias[c], b1 = bias[c + 1];
            #pragma unroll
            for (int im = 0; im < 4; im++) {
                const int r1 = row0 + wm + im * 16 + (lane >> 2);
                float2 v1, v2;
                v1.x = tf32r(fmaxf(acc[im][in][0] + b0, 0.f));
                v1.y = tf32r(fmaxf(acc[im][in][1] + b1, 0.f));
                v2.x = tf32r(fmaxf(acc[im][in][2] + b0, 0.f));
                v2.y = tf32r(fmaxf(acc[im][in][3] + b1, 0.f));
                *(float2*)&C[(size_t)r1 * N + c]       = v1;
                *(float2*)&C[(size_t)(r1 + 8) * N + c] = v2;
            }
        }
    } else {
        __syncthreads();                       // done reading smem tiles
        int* smax = (int*)sm;                  // reuse smem: 256 ints
        smax[tid] = 0;
        __syncthreads();
        #pragma unroll
        for (int in = 0; in < 8; in++) {
            const int c = col0 + wn + in * 8 + (lane & 3) * 2;
            const float b0 = bias[c], b1 = bias[c + 1];
            #pragma unroll
            for (int p = 0; p < 2; p++) {
                float m = fmaxf(acc[0][in][p], acc[0][in][p + 2]);
                #pragma unroll
                for (int im = 1; im < 4; im++)
                    m = fmaxf(m, fmaxf(acc[im][in][p], acc[im][in][p + 2]));
                m = fmaxf(m + (p ? b1 : b0), 0.f);
                m = fmaxf(m, __shfl_xor_sync(0xFFFFFFFFu, m, 4));
                m = fmaxf(m, __shfl_xor_sync(0xFFFFFFFFu, m, 8));
                m = fmaxf(m, __shfl_xor_sync(0xFFFFFFFFu, m, 16));
                if ((lane >> 2) == 0)
                    atomicMax(&smax[wn + in * 8 + (lane & 3) * 2 + p], __float_as_int(m));
            }
        }
        __syncthreads();
        {
            const int seg = row0 >> 12;       // 4096 rows per segment
            atomicMax((int*)&C[(size_t)seg * N + col0 + tid], smax[tid]);
        }
    }
}

// ---------------- launch ----------------
extern "C" void kernel_launch(void* const* d_in, const int* in_sizes, int n_in,
                              void* d_out, int out_size) {
    const float* x   = (const float*)d_in[0];
    const float* pos = (const float*)d_in[1];
    const float* W1  = (const float*)d_in[3];
    const float* b1  = (const float*)d_in[4];
    const float* W2  = (const float*)d_in[5];
    const float* b2  = (const float*)d_in[6];
    const float* W3  = (const float*)d_in[7];
    const float* b3  = (const float*)d_in[8];
    float* out = (float*)d_out;

    float *xr, *h1, *h2, *w1r, *w2r, *w3r;
    cudaGetSymbolAddress((void**)&xr,  g_xr);
    cudaGetSymbolAddress((void**)&h1,  g_h1);
    cudaGetSymbolAddress((void**)&h2,  g_h2);
    cudaGetSymbolAddress((void**)&w1r, g_w1r);
    cudaGetSymbolAddress((void**)&w2r, g_w2r);
    cudaGetSymbolAddress((void**)&w3r, g_w3r);

    cudaFuncSetAttribute(tc_gemm<0>, cudaFuncAttributeMaxDynamicSharedMemorySize, SMEM_BYTES);
    cudaFuncSetAttribute(tc_gemm<1>, cudaFuncAttributeMaxDynamicSharedMemorySize, SMEM_BYTES);

    prep_x_kernel<<<(MPTS * 288 + 255) / 256, 256>>>(x, pos, xr, out, 32 * 1024);
    wround_kernel<<<(288 * 256 + 255) / 256, 256>>>(W1, w1r, 259, 256, 288);
    wround_kernel<<<(256 * 512 + 255) / 256, 256>>>(W2, w2r, 256, 512, 256);
    wround_kernel<<<(512 * 1024 + 255) / 256, 256>>>(W3, w3r, 512, 1024, 512);

    // L1: [131072,288] @ [288,256] -> h1
    tc_gemm<0><<<dim3(256 / BN, MPTS / BM), 256, SMEM_BYTES>>>(xr, w1r, b1, h1, 256, 288, 9);
    // L2: [131072,256] @ [256,512] -> h2
    tc_gemm<0><<<dim3(512 / BN, MPTS / BM), 256, SMEM_BYTES>>>(h1, w2r, b2, h2, 512, 256, 8);
    // L3: [131072,512] @ [512,1024] -> fused segment max -> out[32,1024]
    tc_gemm<1><<<dim3(1024 / BN, MPTS / BM), 256, SMEM_BYTES>>>(h2, w3r, b3, out, 1024, 512, 16);
}

// round 8
// speedup vs baseline: 1.8549x; 1.8549x over previous
#include <cuda_runtime.h>
#include <cuda_fp16.h>
#include <cstdint>

#define MPTS 131072
#define BM 128
#define BN 128
#define BK 64                       // halves per k-chunk
#define STAGES 3
#define PITCH 72                    // smem row pitch in halves: 144B = 9*16B (odd) -> ldmatrix conflict-free
#define STAGE_F (128 * PITCH)       // halves per tile (A and B identical: 128 rows)
#define SMEM_BYTES (STAGES * 2 * STAGE_F * 2)   // 110592 B

// ---- scratch (device globals; no allocation allowed) ----
__device__ __half g_xh[(size_t)MPTS * 320];   // [x|pos|0] padded K=320, fp16
__device__ __half g_h1[(size_t)MPTS * 256];
__device__ __half g_h2[(size_t)MPTS * 512];
__device__ __half g_w1t[256 * 320];           // W^T [N][K] fp16, zero-padded
__device__ __half g_w2t[512 * 256];
__device__ __half g_w3t[1024 * 512];

// ---------------- helpers ----------------
__device__ __forceinline__ uint32_t s2u(const void* p) {
    uint32_t a;
    asm("{ .reg .u64 t; cvta.to.shared.u64 t, %1; cvt.u32.u64 %0, t; }" : "=r"(a) : "l"(p));
    return a;
}
__device__ __forceinline__ void cp16(uint32_t dst, const void* src) {
    asm volatile("cp.async.cg.shared.global [%0], [%1], 16;" :: "r"(dst), "l"(src));
}
__device__ __forceinline__ void ldsm4(uint32_t* r, uint32_t addr) {
    asm volatile("ldmatrix.sync.aligned.m8n8.x4.shared.b16 {%0,%1,%2,%3}, [%4];"
        : "=r"(r[0]), "=r"(r[1]), "=r"(r[2]), "=r"(r[3]) : "r"(addr));
}
__device__ __forceinline__ void mma16(float* c, const uint32_t* a, const uint32_t* b) {
    asm volatile("mma.sync.aligned.m16n8k16.row.col.f32.f16.f16.f32 "
        "{%0,%1,%2,%3}, {%4,%5,%6,%7}, {%8,%9}, {%0,%1,%2,%3};"
        : "+f"(c[0]), "+f"(c[1]), "+f"(c[2]), "+f"(c[3])
        : "r"(a[0]), "r"(a[1]), "r"(a[2]), "r"(a[3]), "r"(b[0]), "r"(b[1]));
}

// ---------------- prep kernels ----------------
__global__ void prep_x_kernel(const float* __restrict__ x, const float* __restrict__ pos,
                              __half* __restrict__ xh, float* __restrict__ out, int out_n) {
    int i = blockIdx.x * blockDim.x + threadIdx.x;
    if (i < out_n) out[i] = 0.0f;
    if (i >= MPTS * 320) return;
    int r = i / 320, c = i % 320;
    float v = 0.0f;
    if (c < 256)      v = x[(size_t)r * 256 + c];
    else if (c < 259) v = pos[(size_t)r * 3 + (c - 256)];
    xh[i] = __float2half_rn(v);
}
// Wt[n][k] = fp16(W[k][n]), zero-padded to KP
__global__ void wtrans_kernel(const float* __restrict__ W, __half* __restrict__ Wt,
                              int K, int N, int KP) {
    int i = blockIdx.x * blockDim.x + threadIdx.x;
    if (i >= N * KP) return;
    int n = i / KP, k = i % KP;
    Wt[i] = __float2half_rn((k < K) ? W[(size_t)k * N + n] : 0.0f);
}

// ---------------- fused GEMM: C = relu(A @ B + bias) ----------------
// A [M, lda] fp16 row-major, Bt [N, ldb] fp16 (W transposed, n-major).
// CTA 128x128, BK=64, warps 2x4 (warp tile 64x32), 3-stage cp.async, ldmatrix frags.
// SEGMAX=0: store fp16 activations. SEGMAX=1: f32 atomicMax segment epilogue.
template<int SEGMAX>
__global__ __launch_bounds__(256, 2)
void tc_gemm(const __half* __restrict__ A, const __half* __restrict__ Bt,
             const float* __restrict__ bias, void* __restrict__ Cv,
             int N, int lda, int ldb, int nCh)
{
    extern __shared__ __half sh[];
    __half* As = sh;
    __half* Bs = sh + STAGES * STAGE_F;
    const uint32_t sbA = s2u(As), sbB = s2u(Bs);
    const int tid = threadIdx.x;
    const int lane = tid & 31, wid = tid >> 5;
    const int wm = (wid >> 2) * 64;
    const int wn = (wid & 3) * 32;
    const int row0 = blockIdx.y * BM, col0 = blockIdx.x * BN;

    float acc[4][4][4];
    #pragma unroll
    for (int i = 0; i < 4; i++)
        #pragma unroll
        for (int j = 0; j < 4; j++)
            #pragma unroll
            for (int k = 0; k < 4; k++) acc[i][j][k] = 0.0f;

    // per-lane ldmatrix base offsets (halves)
    const int a_row = ((lane >> 3) & 1) * 8 + (lane & 7);
    const int a_col = ((lane >> 4) & 1) * 8;
    const int b_row = ((lane >> 4) & 1) * 8 + (lane & 7);
    const int b_col = ((lane >> 3) & 1) * 8;

    auto load_stage = [&](int kc, int s) {
        const int kb = kc * BK;
        #pragma unroll
        for (int i = 0; i < 4; i++) {          // A: 128 rows x 8 chunks of 16B
            int idx = i * 256 + tid;
            int r = idx >> 3, c8 = idx & 7;
            cp16(sbA + (s * STAGE_F + r * PITCH + c8 * 8) * 2,
                 &A[(size_t)(row0 + r) * lda + kb + c8 * 8]);
        }
        #pragma unroll
        for (int i = 0; i < 4; i++) {          // B: 128 n-rows x 8 chunks
            int idx = i * 256 + tid;
            int r = idx >> 3, c8 = idx & 7;
            cp16(sbB + (s * STAGE_F + r * PITCH + c8 * 8) * 2,
                 &Bt[(size_t)(col0 + r) * ldb + kb + c8 * 8]);
        }
        asm volatile("cp.async.commit_group;" ::: "memory");
    };

    load_stage(0, 0);
    load_stage(1, 1);

    for (int kc = 0; kc < nCh; kc++) {
        if (kc + 1 < nCh) asm volatile("cp.async.wait_group 1;" ::: "memory");
        else              asm volatile("cp.async.wait_group 0;" ::: "memory");
        __syncthreads();
        if (kc + 2 < nCh) load_stage(kc + 2, (kc + 2) % STAGES);

        const uint32_t aBase = sbA + ((kc % STAGES) * STAGE_F) * 2;
        const uint32_t bBase = sbB + ((kc % STAGES) * STAGE_F) * 2;
        #pragma unroll
        for (int kq = 0; kq < 4; kq++) {       // 4 x k16 per 64-chunk
            const int k0 = kq * 16;
            uint32_t af[4][4], bf[4][2];
            #pragma unroll
            for (int im = 0; im < 4; im++)
                ldsm4(af[im], aBase + ((wm + im * 16 + a_row) * PITCH + a_col + k0) * 2);
            #pragma unroll
            for (int ip = 0; ip < 2; ip++) {   // x4 covers 2 n-blocks
                uint32_t t[4];
                ldsm4(t, bBase + ((wn + ip * 16 + b_row) * PITCH + b_col + k0) * 2);
                bf[ip * 2][0] = t[0]; bf[ip * 2][1] = t[1];
                bf[ip * 2 + 1][0] = t[2]; bf[ip * 2 + 1][1] = t[3];
            }
            #pragma unroll
            for (int im = 0; im < 4; im++)
                #pragma unroll
                for (int in = 0; in < 4; in++)
                    mma16(acc[im][in], af[im], bf[in]);
        }
    }

    // ---- epilogue ----
    if (!SEGMAX) {
        __half* C = (__half*)Cv;
        #pragma unroll
        for (int in = 0; in < 4; in++) {
            const int c = col0 + wn + in * 8 + (lane & 3) * 2;
            const float b0 = bias[c], b1 = bias[c + 1];
            #pragma unroll
            for (int im = 0; im < 4; im++) {
                const int r1 = row0 + wm + im * 16 + (lane >> 2);
                __half2 v1 = __halves2half2(__float2half_rn(fmaxf(acc[im][in][0] + b0, 0.f)),
                                            __float2half_rn(fmaxf(acc[im][in][1] + b1, 0.f)));
                __half2 v2 = __halves2half2(__float2half_rn(fmaxf(acc[im][in][2] + b0, 0.f)),
                                            __float2half_rn(fmaxf(acc[im][in][3] + b1, 0.f)));
                *(__half2*)&C[(size_t)r1 * N + c]       = v1;
                *(__half2*)&C[(size_t)(r1 + 8) * N + c] = v2;
            }
        }
    } else {
        float* C = (float*)Cv;
        __syncthreads();                       // done reading smem tiles
        int* smax = (int*)sh;                  // reuse smem: 128 ints
        if (tid < 128) smax[tid] = 0;
        __syncthreads();
        #pragma unroll
        for (int in = 0; in < 4; in++) {
            const int c = col0 + wn + in * 8 + (lane & 3) * 2;
            const float b0 = bias[c], b1 = bias[c + 1];
            #pragma unroll
            for (int p = 0; p < 2; p++) {
                float m = fmaxf(acc[0][in][p], acc[0][in][p + 2]);
                #pragma unroll
                for (int im = 1; im < 4; im++)
                    m = fmaxf(m, fmaxf(acc[im][in][p], acc[im][in][p + 2]));
                m = fmaxf(m + (p ? b1 : b0), 0.f);
                m = fmaxf(m, __shfl_xor_sync(0xFFFFFFFFu, m, 4));
                m = fmaxf(m, __shfl_xor_sync(0xFFFFFFFFu, m, 8));
                m = fmaxf(m, __shfl_xor_sync(0xFFFFFFFFu, m, 16));
                if ((lane >> 2) == 0)
                    atomicMax(&smax[wn + in * 8 + (lane & 3) * 2 + p], __float_as_int(m));
            }
        }
        __syncthreads();
        if (tid < 128) {
            const int seg = row0 >> 12;       // 4096 rows per segment
            atomicMax((int*)&C[(size_t)seg * N + col0 + tid], smax[tid]);
        }
    }
}

// ---------------- launch ----------------
extern "C" void kernel_launch(void* const* d_in, const int* in_sizes, int n_in,
                              void* d_out, int out_size) {
    const float* x   = (const float*)d_in[0];
    const float* pos = (const float*)d_in[1];
    const float* W1  = (const float*)d_in[3];
    const float* b1  = (const float*)d_in[4];
    const float* W2  = (const float*)d_in[5];
    const float* b2  = (const float*)d_in[6];
    const float* W3  = (const float*)d_in[7];
    const float* b3  = (const float*)d_in[8];
    float* out = (float*)d_out;

    __half *xh, *h1, *h2, *w1t, *w2t, *w3t;
    cudaGetSymbolAddress((void**)&xh,  g_xh);
    cudaGetSymbolAddress((void**)&h1,  g_h1);
    cudaGetSymbolAddress((void**)&h2,  g_h2);
    cudaGetSymbolAddress((void**)&w1t, g_w1t);
    cudaGetSymbolAddress((void**)&w2t, g_w2t);
    cudaGetSymbolAddress((void**)&w3t, g_w3t);

    cudaFuncSetAttribute(tc_gemm<0>, cudaFuncAttributeMaxDynamicSharedMemorySize, SMEM_BYTES);
    cudaFuncSetAttribute(tc_gemm<1>, cudaFuncAttributeMaxDynamicSharedMemorySize, SMEM_BYTES);

    prep_x_kernel<<<(MPTS * 320 + 255) / 256, 256>>>(x, pos, xh, out, 32 * 1024);
    wtrans_kernel<<<(256 * 320 + 255) / 256, 256>>>(W1, w1t, 259, 256, 320);
    wtrans_kernel<<<(512 * 256 + 255) / 256, 256>>>(W2, w2t, 256, 512, 256);
    wtrans_kernel<<<(1024 * 512 + 255) / 256, 256>>>(W3, w3t, 512, 1024, 512);

    // L1: [131072,320] @ W1t[256,320] -> h1 (fp16)
    tc_gemm<0><<<dim3(256 / BN, MPTS / BM), 256, SMEM_BYTES>>>(xh, w1t, b1, h1, 256, 320, 320, 5);
    // L2: [131072,256] @ W2t[512,256] -> h2 (fp16)
    tc_gemm<0><<<dim3(512 / BN, MPTS / BM), 256, SMEM_BYTES>>>(h1, w2t, b2, h2, 512, 256, 256, 4);
    // L3: [131072,512] @ W3t[1024,512] -> fused segment max -> out[32,1024] f32
    tc_gemm<1><<<dim3(1024 / BN, MPTS / BM), 256, SMEM_BYTES>>>(h2, w3t, b3, out, 1024, 512, 512, 8);
}